// round 4
// baseline (speedup 1.0000x reference)
#include <cuda_runtime.h>
#include <cuda_bf16.h>
#include <cstdint>

// Problem constants
#define BDIM 2
#define LSEQ 8192
#define CDIM 512
#define KWIN 17
#define HALFK 8
#define NTOK (BDIM * LSEQ)      // 16384

// ---------------------------------------------------------------------------
// Scratch (__device__ globals; no cudaMalloc allowed)
// ---------------------------------------------------------------------------
__device__ float          g_qkv[(size_t)NTOK * 3 * CDIM];     // 96 MB fp32
__device__ __nv_bfloat16  g_xhi[(size_t)NTOK * CDIM];
__device__ __nv_bfloat16  g_xlo[(size_t)NTOK * CDIM];
__device__ __nv_bfloat16  g_ahi[(size_t)NTOK * CDIM];
__device__ __nv_bfloat16  g_alo[(size_t)NTOK * CDIM];
__device__ __nv_bfloat16  g_wqhi[(size_t)3 * CDIM * CDIM];    // [1536][512] = w_qkv^T
__device__ __nv_bfloat16  g_wqlo[(size_t)3 * CDIM * CDIM];
__device__ __nv_bfloat16  g_wohi[(size_t)CDIM * CDIM];        // [512][512]  = w_out^T
__device__ __nv_bfloat16  g_wolo[(size_t)CDIM * CDIM];

// ---------------------------------------------------------------------------
// helpers
// ---------------------------------------------------------------------------
__device__ __forceinline__ uint32_t smem_u32(const void* p) {
    uint32_t a;
    asm("{ .reg .u64 t; cvta.to.shared.u64 t, %1; cvt.u32.u64 %0, t; }" : "=r"(a) : "l"(p));
    return a;
}
__device__ __forceinline__ void cp16(uint32_t dst, const void* src) {
    asm volatile("cp.async.cg.shared.global [%0], [%1], 16;" :: "r"(dst), "l"(src));
}
__device__ __forceinline__ void ldsm_x4(uint32_t* r, uint32_t addr) {
    asm volatile("ldmatrix.sync.aligned.m8n8.x4.shared.b16 {%0,%1,%2,%3}, [%4];"
                 : "=r"(r[0]), "=r"(r[1]), "=r"(r[2]), "=r"(r[3]) : "r"(addr));
}
__device__ __forceinline__ void ldsm_x2(uint32_t* r, uint32_t addr) {
    asm volatile("ldmatrix.sync.aligned.m8n8.x2.shared.b16 {%0,%1}, [%2];"
                 : "=r"(r[0]), "=r"(r[1]) : "r"(addr));
}
__device__ __forceinline__ void mma_bf16(float* c, const uint32_t* a, const uint32_t* b) {
    asm volatile(
        "mma.sync.aligned.m16n8k16.row.col.f32.bf16.bf16.f32 "
        "{%0,%1,%2,%3}, {%4,%5,%6,%7}, {%8,%9}, {%0,%1,%2,%3};"
        : "+f"(c[0]), "+f"(c[1]), "+f"(c[2]), "+f"(c[3])
        : "r"(a[0]), "r"(a[1]), "r"(a[2]), "r"(a[3]), "r"(b[0]), "r"(b[1]));
}

// ---------------------------------------------------------------------------
// Split-bf16 GEMM via mma.sync.  C[M,Ntot] fp32 = (Ahi+Alo)[M,512] @ (B)^T,
// B* stored [Ntot, 512] row-major bf16.  D = Ahi*Bhi + Ahi*Blo + Alo*Bhi.
// Block 128x128, 16 warps (4x4), warp 32x32, BK=32 double-buffered cp.async.
// SMEM rows padded to 80B pitch -> conflict-free ldmatrix.
// ---------------------------------------------------------------------------
#define GK       512
#define BK       32
#define NSTG     (GK / BK)          // 16
#define PITCH    80                 // bytes per 32-bf16 row (64B data + 16B pad)
#define A_SZ     (128 * PITCH)      // 10240
#define STG_SZ   (4 * A_SZ)         // Ahi|Alo|Bhi|Blo = 40960
#define GEMM_SMEM (2 * STG_SZ)      // 81920

__global__ __launch_bounds__(512) void gemm_mma(
    const __nv_bfloat16* __restrict__ Ahi, const __nv_bfloat16* __restrict__ Alo,
    const __nv_bfloat16* __restrict__ Bhi, const __nv_bfloat16* __restrict__ Blo,
    float* __restrict__ C, int Ntot)
{
    extern __shared__ char smem[];
    const uint32_t sb = smem_u32(smem);
    const int tid  = threadIdx.x;
    const int wid  = tid >> 5;
    const int lane = tid & 31;
    const int bm = blockIdx.y * 128;
    const int bn = blockIdx.x * 128;
    const int warp_m = (wid >> 2) * 32;     // 0,32,64,96
    const int warp_n = (wid & 3) * 32;      // 0,32,64,96

    // ---- async stage loader: 512 threads, 1 x 16B chunk per matrix each ----
    const int lrow = tid >> 2;              // 0..127
    const int lc16 = (tid & 3) * 16;        // byte col 0..48
    auto load_stage = [&](int s, int b) {
        const int k0 = s * BK;
        const uint32_t buf = sb + (uint32_t)b * STG_SZ;
        const uint32_t off = (uint32_t)(lrow * PITCH + lc16);
        const size_t ga = (size_t)(bm + lrow) * GK + k0 + (lc16 >> 1);
        const size_t gb = (size_t)(bn + lrow) * GK + k0 + (lc16 >> 1);
        cp16(buf + off,            Ahi + ga);
        cp16(buf + A_SZ + off,     Alo + ga);
        cp16(buf + 2 * A_SZ + off, Bhi + gb);
        cp16(buf + 3 * A_SZ + off, Blo + gb);
        asm volatile("cp.async.commit_group;" ::: "memory");
    };

    float acc[2][4][4];                     // [mi][ni][frag]
    #pragma unroll
    for (int mi = 0; mi < 2; mi++)
        #pragma unroll
        for (int ni = 0; ni < 4; ni++)
            #pragma unroll
            for (int f = 0; f < 4; f++) acc[mi][ni][f] = 0.f;

    // ldmatrix lane address components (within a stage buffer)
    const uint32_t aLane = (uint32_t)((warp_m + (lane & 15)) * PITCH + ((lane >> 4) & 1) * 16);
    const uint32_t bLane = (uint32_t)((warp_n + (lane & 7)) * PITCH + ((lane >> 3) & 1) * 16);

    load_stage(0, 0);
    load_stage(1, 1);

    for (int s = 0; s < NSTG; s++) {
        const int b = s & 1;
        if (s + 1 < NSTG) asm volatile("cp.async.wait_group 1;" ::: "memory");
        else              asm volatile("cp.async.wait_group 0;" ::: "memory");
        __syncthreads();

        const uint32_t buf = sb + (uint32_t)b * STG_SZ;
        #pragma unroll
        for (int kk = 0; kk < 2; kk++) {            // two k16 steps per stage
            const uint32_t ko = (uint32_t)(kk * 32);
            uint32_t af[2][4], bfh[4][2], bfl[4][2];
            #pragma unroll
            for (int mi = 0; mi < 2; mi++)
                ldsm_x4(af[mi], buf + aLane + (uint32_t)(mi * 16 * PITCH) + ko);          // Ahi
            #pragma unroll
            for (int ni = 0; ni < 4; ni++) {
                ldsm_x2(bfh[ni], buf + 2 * A_SZ + bLane + (uint32_t)(ni * 8 * PITCH) + ko); // Bhi
                ldsm_x2(bfl[ni], buf + 3 * A_SZ + bLane + (uint32_t)(ni * 8 * PITCH) + ko); // Blo
            }
            #pragma unroll
            for (int mi = 0; mi < 2; mi++)
                #pragma unroll
                for (int ni = 0; ni < 4; ni++) {
                    mma_bf16(acc[mi][ni], af[mi], bfh[ni]);   // hi*hi
                    mma_bf16(acc[mi][ni], af[mi], bfl[ni]);   // hi*lo
                }
            #pragma unroll
            for (int mi = 0; mi < 2; mi++)
                ldsm_x4(af[mi], buf + A_SZ + aLane + (uint32_t)(mi * 16 * PITCH) + ko);   // Alo
            #pragma unroll
            for (int mi = 0; mi < 2; mi++)
                #pragma unroll
                for (int ni = 0; ni < 4; ni++)
                    mma_bf16(acc[mi][ni], af[mi], bfh[ni]);   // lo*hi
        }
        __syncthreads();
        if (s + 2 < NSTG) load_stage(s + 2, b);
    }

    // ---- epilogue: fp32 direct store ----
    const int er = lane >> 2;            // 0..7
    const int ec = (lane & 3) * 2;       // 0,2,4,6
    #pragma unroll
    for (int mi = 0; mi < 2; mi++) {
        #pragma unroll
        for (int ni = 0; ni < 4; ni++) {
            float* p0 = C + (size_t)(bm + warp_m + mi * 16 + er) * Ntot + bn + warp_n + ni * 8 + ec;
            *(float2*)p0                      = make_float2(acc[mi][ni][0], acc[mi][ni][1]);
            *(float2*)(p0 + (size_t)8 * Ntot) = make_float2(acc[mi][ni][2], acc[mi][ni][3]);
        }
    }
}

// ---------------------------------------------------------------------------
// fp32 -> (hi, lo) bf16 split, elementwise
// ---------------------------------------------------------------------------
__global__ __launch_bounds__(256) void split_kernel(const float* __restrict__ src,
                                                    __nv_bfloat16* __restrict__ hi,
                                                    __nv_bfloat16* __restrict__ lo)
{
    const size_t i = ((size_t)blockIdx.x * blockDim.x + threadIdx.x) * 4;
    float4 v = *(const float4*)(src + i);
    __nv_bfloat16 h0 = __float2bfloat16(v.x), h1 = __float2bfloat16(v.y);
    __nv_bfloat16 h2 = __float2bfloat16(v.z), h3 = __float2bfloat16(v.w);
    __nv_bfloat16 l0 = __float2bfloat16(v.x - __bfloat162float(h0));
    __nv_bfloat16 l1 = __float2bfloat16(v.y - __bfloat162float(h1));
    __nv_bfloat16 l2 = __float2bfloat16(v.z - __bfloat162float(h2));
    __nv_bfloat16 l3 = __float2bfloat16(v.w - __bfloat162float(h3));
    *(__nv_bfloat162*)(hi + i)     = __nv_bfloat162(h0, h1);
    *(__nv_bfloat162*)(hi + i + 2) = __nv_bfloat162(h2, h3);
    *(__nv_bfloat162*)(lo + i)     = __nv_bfloat162(l0, l1);
    *(__nv_bfloat162*)(lo + i + 2) = __nv_bfloat162(l2, l3);
}

// ---------------------------------------------------------------------------
// weight transpose + split: w[K,N] fp32 -> hiT/loT [N,K] bf16
// ---------------------------------------------------------------------------
__global__ __launch_bounds__(256) void wsplit_kernel(const float* __restrict__ w,
                                                     __nv_bfloat16* __restrict__ hiT,
                                                     __nv_bfloat16* __restrict__ loT,
                                                     int K, int N)
{
    __shared__ float t[32][33];
    const int k0 = blockIdx.y * 32;
    const int n0 = blockIdx.x * 32;
    const int tx = threadIdx.x, ty = threadIdx.y;
    #pragma unroll
    for (int i = ty; i < 32; i += 8)
        t[i][tx] = w[(size_t)(k0 + i) * N + n0 + tx];
    __syncthreads();
    #pragma unroll
    for (int i = ty; i < 32; i += 8) {
        const float v = t[tx][i];                 // = w[k0+tx][n0+i]
        __nv_bfloat16 h = __float2bfloat16(v);
        __nv_bfloat16 l = __float2bfloat16(v - __bfloat162float(h));
        hiT[(size_t)(n0 + i) * K + k0 + tx] = h;
        loT[(size_t)(n0 + i) * K + k0 + tx] = l;
    }
}

// ---------------------------------------------------------------------------
// Warp-per-token windowed attention; writes split-bf16 (att_hi, att_lo)
// ---------------------------------------------------------------------------
__global__ __launch_bounds__(256) void attn_kernel(const float* __restrict__ x,
                                                   const float* __restrict__ w_width,
                                                   const float* __restrict__ b_width,
                                                   __nv_bfloat16* __restrict__ att_hi,
                                                   __nv_bfloat16* __restrict__ att_lo)
{
    const int gwarp = (blockIdx.x * blockDim.x + threadIdx.x) >> 5;
    const int lane = threadIdx.x & 31;
    if (gwarp >= NTOK) return;

    const int b = gwarp >> 13;            // / LSEQ
    const int l = gwarp & (LSEQ - 1);

    const float* qkv = g_qkv;
    const float* qrow = qkv + (size_t)gwarp * 3 * CDIM;

    float q[16];
    #pragma unroll
    for (int i = 0; i < 16; i++) q[i] = qrow[lane + 32 * i];

    const float* xrow = x + (size_t)gwarp * CDIM;
    float wsum = 0.f;
    #pragma unroll
    for (int i = 0; i < 16; i++)
        wsum += xrow[lane + 32 * i] * w_width[lane + 32 * i];
    #pragma unroll
    for (int o = 16; o > 0; o >>= 1) wsum += __shfl_xor_sync(0xffffffffu, wsum, o);
    const float width = 1.f / (1.f + expf(-(wsum + b_width[0]))) * (float)(KWIN - 1) + 1.f;

    float sc[KWIN];
    #pragma unroll
    for (int j = 0; j < KWIN; j++) {
        const int row = l + j - HALFK;
        float s = 0.f;
        if (row >= 0 && row < LSEQ) {
            const float* krow = qkv + ((size_t)(b * LSEQ + row) * 3 + 1) * CDIM;
            #pragma unroll
            for (int i = 0; i < 16; i++) s += q[i] * krow[lane + 32 * i];
        }
        #pragma unroll
        for (int o = 16; o > 0; o >>= 1) s += __shfl_xor_sync(0xffffffffu, s, o);
        sc[j] = s;
    }

    const float scale = 0.044194173824159216f;
    float mx = -1e30f;
    #pragma unroll
    for (int j = 0; j < KWIN; j++) {
        const float rel = fabsf((float)j - (float)HALFK);
        const float m = 1.f / (1.f + expf(-(width - rel) * 5.f));
        sc[j] = sc[j] * scale - (1.f - m) * 10000.f;
        mx = fmaxf(mx, sc[j]);
    }
    float denom = 0.f;
    #pragma unroll
    for (int j = 0; j < KWIN; j++) {
        sc[j] = expf(sc[j] - mx);
        denom += sc[j];
    }
    const float inv = 1.f / denom;

    float acc[16];
    const float* vself = qkv + ((size_t)gwarp * 3 + 2) * CDIM;
    #pragma unroll
    for (int i = 0; i < 16; i++) acc[i] = vself[lane + 32 * i];

    #pragma unroll
    for (int j = 0; j < KWIN; j++) {
        const int row = l + j - HALFK;
        if (row < 0 || row >= LSEQ) continue;
        const float a = sc[j] * inv;
        const float* vrow = qkv + ((size_t)(b * LSEQ + row) * 3 + 2) * CDIM;
        #pragma unroll
        for (int i = 0; i < 16; i++) acc[i] += a * vrow[lane + 32 * i];
    }

    __nv_bfloat16* hrow = att_hi + (size_t)gwarp * CDIM;
    __nv_bfloat16* lrow = att_lo + (size_t)gwarp * CDIM;
    #pragma unroll
    for (int i = 0; i < 16; i++) {
        const float v = acc[i];
        __nv_bfloat16 h = __float2bfloat16(v);
        hrow[lane + 32 * i] = h;
        lrow[lane + 32 * i] = __float2bfloat16(v - __bfloat162float(h));
    }
}

// ---------------------------------------------------------------------------
extern "C" void kernel_launch(void* const* d_in, const int* in_sizes, int n_in,
                              void* d_out, int out_size)
{
    const float* x       = (const float*)d_in[0];
    const float* w_qkv   = (const float*)d_in[1];
    const float* w_width = (const float*)d_in[2];
    const float* b_width = (const float*)d_in[3];
    const float* w_out   = (const float*)d_in[4];
    float* out = (float*)d_out;

    float* qkv;          cudaGetSymbolAddress((void**)&qkv,  g_qkv);
    __nv_bfloat16* xhi;  cudaGetSymbolAddress((void**)&xhi,  g_xhi);
    __nv_bfloat16* xlo;  cudaGetSymbolAddress((void**)&xlo,  g_xlo);
    __nv_bfloat16* ahi;  cudaGetSymbolAddress((void**)&ahi,  g_ahi);
    __nv_bfloat16* alo;  cudaGetSymbolAddress((void**)&alo,  g_alo);
    __nv_bfloat16* wqhi; cudaGetSymbolAddress((void**)&wqhi, g_wqhi);
    __nv_bfloat16* wqlo; cudaGetSymbolAddress((void**)&wqlo, g_wqlo);
    __nv_bfloat16* wohi; cudaGetSymbolAddress((void**)&wohi, g_wohi);
    __nv_bfloat16* wolo; cudaGetSymbolAddress((void**)&wolo, g_wolo);

    cudaFuncSetAttribute(gemm_mma, cudaFuncAttributeMaxDynamicSharedMemorySize, GEMM_SMEM);

    // 0) input splits
    split_kernel<<<(NTOK * CDIM) / (256 * 4), 256>>>(x, xhi, xlo);
    {
        dim3 g(3 * CDIM / 32, CDIM / 32);
        wsplit_kernel<<<g, dim3(32, 8)>>>(w_qkv, wqhi, wqlo, CDIM, 3 * CDIM);
    }
    {
        dim3 g(CDIM / 32, CDIM / 32);
        wsplit_kernel<<<g, dim3(32, 8)>>>(w_out, wohi, wolo, CDIM, CDIM);
    }

    // 1) qkv = x @ w_qkv   (M=16384, N=1536, K=512)
    {
        dim3 grid(3 * CDIM / 128, NTOK / 128);
        gemm_mma<<<grid, 512, GEMM_SMEM>>>(xhi, xlo, wqhi, wqlo, qkv, 3 * CDIM);
    }

    // 2) fused windowed attention -> att_hi/att_lo (bf16 split)
    attn_kernel<<<NTOK / 8, 256>>>(x, w_width, b_width, ahi, alo);

    // 3) out = att @ w_out  (M=16384, N=512, K=512)
    {
        dim3 grid(CDIM / 128, NTOK / 128);
        gemm_mma<<<grid, 512, GEMM_SMEM>>>(ahi, alo, wohi, wolo, out, CDIM);
    }
}

// round 5
// speedup vs baseline: 1.7051x; 1.7051x over previous
#include <cuda_runtime.h>
#include <cuda_bf16.h>
#include <cstdint>

// Problem constants
#define BDIM 2
#define LSEQ 8192
#define CDIM 512
#define KWIN 17
#define HALFK 8
#define NTOK (BDIM * LSEQ)      // 16384

// ---------------------------------------------------------------------------
// Scratch (__device__ globals; no cudaMalloc allowed)
// ---------------------------------------------------------------------------
__device__ float          g_qkv[(size_t)NTOK * 3 * CDIM];     // 96 MB fp32
__device__ __nv_bfloat16  g_xhi[(size_t)NTOK * CDIM];
__device__ __nv_bfloat16  g_xlo[(size_t)NTOK * CDIM];
__device__ __nv_bfloat16  g_ahi[(size_t)NTOK * CDIM];
__device__ __nv_bfloat16  g_alo[(size_t)NTOK * CDIM];
__device__ __nv_bfloat16  g_wqhi[(size_t)3 * CDIM * CDIM];    // [1536][512] = w_qkv^T
__device__ __nv_bfloat16  g_wqlo[(size_t)3 * CDIM * CDIM];
__device__ __nv_bfloat16  g_wohi[(size_t)CDIM * CDIM];        // [512][512]  = w_out^T
__device__ __nv_bfloat16  g_wolo[(size_t)CDIM * CDIM];

// ---------------------------------------------------------------------------
// helpers
// ---------------------------------------------------------------------------
__device__ __forceinline__ uint32_t smem_u32(const void* p) {
    uint32_t a;
    asm("{ .reg .u64 t; cvta.to.shared.u64 t, %1; cvt.u32.u64 %0, t; }" : "=r"(a) : "l"(p));
    return a;
}
__device__ __forceinline__ void cp16(uint32_t dst, const void* src) {
    asm volatile("cp.async.cg.shared.global [%0], [%1], 16;" :: "r"(dst), "l"(src));
}
__device__ __forceinline__ void ldsm_x4(uint32_t* r, uint32_t addr) {
    asm volatile("ldmatrix.sync.aligned.m8n8.x4.shared.b16 {%0,%1,%2,%3}, [%4];"
                 : "=r"(r[0]), "=r"(r[1]), "=r"(r[2]), "=r"(r[3]) : "r"(addr));
}
__device__ __forceinline__ void ldsm_x2(uint32_t* r, uint32_t addr) {
    asm volatile("ldmatrix.sync.aligned.m8n8.x2.shared.b16 {%0,%1}, [%2];"
                 : "=r"(r[0]), "=r"(r[1]) : "r"(addr));
}
__device__ __forceinline__ void mma_bf16(float* c, const uint32_t* a, const uint32_t* b) {
    asm volatile(
        "mma.sync.aligned.m16n8k16.row.col.f32.bf16.bf16.f32 "
        "{%0,%1,%2,%3}, {%4,%5,%6,%7}, {%8,%9}, {%0,%1,%2,%3};"
        : "+f"(c[0]), "+f"(c[1]), "+f"(c[2]), "+f"(c[3])
        : "r"(a[0]), "r"(a[1]), "r"(a[2]), "r"(a[3]), "r"(b[0]), "r"(b[1]));
}

// ---------------------------------------------------------------------------
// Split-bf16 GEMM via mma.sync.  C[M,Ntot] fp32 = (Ahi+Alo)[M,512] @ (B)^T,
// B* stored [Ntot, 512] row-major bf16.  D = Ahi*Bhi + Ahi*Blo + Alo*Bhi.
// Block 128x128, 8 warps (2x4), warp 64x32, BK=32 double-buffered cp.async.
// __launch_bounds__(256, 2): 2 CTAs/SM -> independent barrier domains overlap.
// SMEM rows padded to 80B pitch -> conflict-free ldmatrix.
// ---------------------------------------------------------------------------
#define GK       512
#define BK       32
#define NSTG     (GK / BK)          // 16
#define PITCH    80                 // bytes per 32-bf16 row (64B data + 16B pad)
#define A_SZ     (128 * PITCH)      // 10240
#define STG_SZ   (4 * A_SZ)         // Ahi|Alo|Bhi|Blo = 40960
#define GEMM_SMEM (2 * STG_SZ)      // 81920

__global__ __launch_bounds__(256, 2) void gemm_mma(
    const __nv_bfloat16* __restrict__ Ahi, const __nv_bfloat16* __restrict__ Alo,
    const __nv_bfloat16* __restrict__ Bhi, const __nv_bfloat16* __restrict__ Blo,
    float* __restrict__ C, int Ntot)
{
    extern __shared__ char smem[];
    const uint32_t sb = smem_u32(smem);
    const int tid  = threadIdx.x;
    const int wid  = tid >> 5;
    const int lane = tid & 31;
    const int bm = blockIdx.y * 128;
    const int bn = blockIdx.x * 128;
    const int warp_m = (wid >> 2) * 64;     // 0 or 64
    const int warp_n = (wid & 3) * 32;      // 0,32,64,96

    // ---- async stage loader ----
    const int lrow = tid >> 2;              // 0..63
    const int lc16 = (tid & 3) * 16;        // byte col 0..48
    auto load_stage = [&](int s, int b) {
        const int k0 = s * BK;
        const uint32_t buf = sb + (uint32_t)b * STG_SZ;
        #pragma unroll
        for (int r = 0; r < 2; r++) {
            const int row = lrow + r * 64;
            const uint32_t off = (uint32_t)(row * PITCH + lc16);
            const size_t ga = (size_t)(bm + row) * GK + k0 + (lc16 >> 1);
            const size_t gb = (size_t)(bn + row) * GK + k0 + (lc16 >> 1);
            cp16(buf + off,            Ahi + ga);
            cp16(buf + A_SZ + off,     Alo + ga);
            cp16(buf + 2 * A_SZ + off, Bhi + gb);
            cp16(buf + 3 * A_SZ + off, Blo + gb);
        }
        asm volatile("cp.async.commit_group;" ::: "memory");
    };

    float acc[4][4][4];                     // [mi][ni][frag]
    #pragma unroll
    for (int mi = 0; mi < 4; mi++)
        #pragma unroll
        for (int ni = 0; ni < 4; ni++)
            #pragma unroll
            for (int f = 0; f < 4; f++) acc[mi][ni][f] = 0.f;

    // ldmatrix lane address components (within a stage buffer)
    const uint32_t aLane = (uint32_t)((warp_m + (lane & 15)) * PITCH + ((lane >> 4) & 1) * 16);
    const uint32_t bLane = (uint32_t)((warp_n + (lane & 7)) * PITCH + ((lane >> 3) & 1) * 16);

    load_stage(0, 0);
    load_stage(1, 1);

    for (int s = 0; s < NSTG; s++) {
        const int b = s & 1;
        if (s + 1 < NSTG) asm volatile("cp.async.wait_group 1;" ::: "memory");
        else              asm volatile("cp.async.wait_group 0;" ::: "memory");
        __syncthreads();

        const uint32_t buf = sb + (uint32_t)b * STG_SZ;
        #pragma unroll
        for (int kk = 0; kk < 2; kk++) {            // two k16 steps per stage
            const uint32_t ko = (uint32_t)(kk * 32);
            uint32_t af[4][4], bfh[4][2], bfl[4][2];
            #pragma unroll
            for (int mi = 0; mi < 4; mi++)
                ldsm_x4(af[mi], buf + aLane + (uint32_t)(mi * 16 * PITCH) + ko);          // Ahi
            #pragma unroll
            for (int ni = 0; ni < 4; ni++) {
                ldsm_x2(bfh[ni], buf + 2 * A_SZ + bLane + (uint32_t)(ni * 8 * PITCH) + ko); // Bhi
                ldsm_x2(bfl[ni], buf + 3 * A_SZ + bLane + (uint32_t)(ni * 8 * PITCH) + ko); // Blo
            }
            #pragma unroll
            for (int mi = 0; mi < 4; mi++)
                #pragma unroll
                for (int ni = 0; ni < 4; ni++) {
                    mma_bf16(acc[mi][ni], af[mi], bfh[ni]);   // hi*hi
                    mma_bf16(acc[mi][ni], af[mi], bfl[ni]);   // hi*lo
                }
            #pragma unroll
            for (int mi = 0; mi < 4; mi++)
                ldsm_x4(af[mi], buf + A_SZ + aLane + (uint32_t)(mi * 16 * PITCH) + ko);   // Alo
            #pragma unroll
            for (int mi = 0; mi < 4; mi++)
                #pragma unroll
                for (int ni = 0; ni < 4; ni++)
                    mma_bf16(acc[mi][ni], af[mi], bfh[ni]);   // lo*hi
        }
        __syncthreads();
        if (s + 2 < NSTG) load_stage(s + 2, b);
    }

    // ---- epilogue: fp32 direct store ----
    const int er = lane >> 2;            // 0..7
    const int ec = (lane & 3) * 2;       // 0,2,4,6
    #pragma unroll
    for (int mi = 0; mi < 4; mi++) {
        #pragma unroll
        for (int ni = 0; ni < 4; ni++) {
            float* p0 = C + (size_t)(bm + warp_m + mi * 16 + er) * Ntot + bn + warp_n + ni * 8 + ec;
            *(float2*)p0                      = make_float2(acc[mi][ni][0], acc[mi][ni][1]);
            *(float2*)(p0 + (size_t)8 * Ntot) = make_float2(acc[mi][ni][2], acc[mi][ni][3]);
        }
    }
}

// ---------------------------------------------------------------------------
// fp32 -> (hi, lo) bf16 split, elementwise
// ---------------------------------------------------------------------------
__global__ __launch_bounds__(256) void split_kernel(const float* __restrict__ src,
                                                    __nv_bfloat16* __restrict__ hi,
                                                    __nv_bfloat16* __restrict__ lo)
{
    const size_t i = ((size_t)blockIdx.x * blockDim.x + threadIdx.x) * 4;
    float4 v = *(const float4*)(src + i);
    __nv_bfloat16 h0 = __float2bfloat16(v.x), h1 = __float2bfloat16(v.y);
    __nv_bfloat16 h2 = __float2bfloat16(v.z), h3 = __float2bfloat16(v.w);
    __nv_bfloat16 l0 = __float2bfloat16(v.x - __bfloat162float(h0));
    __nv_bfloat16 l1 = __float2bfloat16(v.y - __bfloat162float(h1));
    __nv_bfloat16 l2 = __float2bfloat16(v.z - __bfloat162float(h2));
    __nv_bfloat16 l3 = __float2bfloat16(v.w - __bfloat162float(h3));
    *(__nv_bfloat162*)(hi + i)     = __nv_bfloat162(h0, h1);
    *(__nv_bfloat162*)(hi + i + 2) = __nv_bfloat162(h2, h3);
    *(__nv_bfloat162*)(lo + i)     = __nv_bfloat162(l0, l1);
    *(__nv_bfloat162*)(lo + i + 2) = __nv_bfloat162(l2, l3);
}

// ---------------------------------------------------------------------------
// weight transpose + split: w[K,N] fp32 -> hiT/loT [N,K] bf16
// ---------------------------------------------------------------------------
__global__ __launch_bounds__(256) void wsplit_kernel(const float* __restrict__ w,
                                                     __nv_bfloat16* __restrict__ hiT,
                                                     __nv_bfloat16* __restrict__ loT,
                                                     int K, int N)
{
    __shared__ float t[32][33];
    const int k0 = blockIdx.y * 32;
    const int n0 = blockIdx.x * 32;
    const int tx = threadIdx.x, ty = threadIdx.y;
    #pragma unroll
    for (int i = ty; i < 32; i += 8)
        t[i][tx] = w[(size_t)(k0 + i) * N + n0 + tx];
    __syncthreads();
    #pragma unroll
    for (int i = ty; i < 32; i += 8) {
        const float v = t[tx][i];                 // = w[k0+tx][n0+i]
        __nv_bfloat16 h = __float2bfloat16(v);
        __nv_bfloat16 l = __float2bfloat16(v - __bfloat162float(h));
        hiT[(size_t)(n0 + i) * K + k0 + tx] = h;
        loT[(size_t)(n0 + i) * K + k0 + tx] = l;
    }
}

// ---------------------------------------------------------------------------
// Warp-per-token windowed attention; writes split-bf16 (att_hi, att_lo)
// ---------------------------------------------------------------------------
__global__ __launch_bounds__(256) void attn_kernel(const float* __restrict__ x,
                                                   const float* __restrict__ w_width,
                                                   const float* __restrict__ b_width,
                                                   __nv_bfloat16* __restrict__ att_hi,
                                                   __nv_bfloat16* __restrict__ att_lo)
{
    const int gwarp = (blockIdx.x * blockDim.x + threadIdx.x) >> 5;
    const int lane = threadIdx.x & 31;
    if (gwarp >= NTOK) return;

    const int b = gwarp >> 13;            // / LSEQ
    const int l = gwarp & (LSEQ - 1);

    const float* qkv = g_qkv;
    const float* qrow = qkv + (size_t)gwarp * 3 * CDIM;

    float q[16];
    #pragma unroll
    for (int i = 0; i < 16; i++) q[i] = qrow[lane + 32 * i];

    const float* xrow = x + (size_t)gwarp * CDIM;
    float wsum = 0.f;
    #pragma unroll
    for (int i = 0; i < 16; i++)
        wsum += xrow[lane + 32 * i] * w_width[lane + 32 * i];
    #pragma unroll
    for (int o = 16; o > 0; o >>= 1) wsum += __shfl_xor_sync(0xffffffffu, wsum, o);
    const float width = 1.f / (1.f + expf(-(wsum + b_width[0]))) * (float)(KWIN - 1) + 1.f;

    float sc[KWIN];
    #pragma unroll
    for (int j = 0; j < KWIN; j++) {
        const int row = l + j - HALFK;
        float s = 0.f;
        if (row >= 0 && row < LSEQ) {
            const float* krow = qkv + ((size_t)(b * LSEQ + row) * 3 + 1) * CDIM;
            #pragma unroll
            for (int i = 0; i < 16; i++) s += q[i] * krow[lane + 32 * i];
        }
        #pragma unroll
        for (int o = 16; o > 0; o >>= 1) s += __shfl_xor_sync(0xffffffffu, s, o);
        sc[j] = s;
    }

    const float scale = 0.044194173824159216f;
    float mx = -1e30f;
    #pragma unroll
    for (int j = 0; j < KWIN; j++) {
        const float rel = fabsf((float)j - (float)HALFK);
        const float m = 1.f / (1.f + expf(-(width - rel) * 5.f));
        sc[j] = sc[j] * scale - (1.f - m) * 10000.f;
        mx = fmaxf(mx, sc[j]);
    }
    float denom = 0.f;
    #pragma unroll
    for (int j = 0; j < KWIN; j++) {
        sc[j] = expf(sc[j] - mx);
        denom += sc[j];
    }
    const float inv = 1.f / denom;

    float acc[16];
    const float* vself = qkv + ((size_t)gwarp * 3 + 2) * CDIM;
    #pragma unroll
    for (int i = 0; i < 16; i++) acc[i] = vself[lane + 32 * i];

    #pragma unroll
    for (int j = 0; j < KWIN; j++) {
        const int row = l + j - HALFK;
        if (row < 0 || row >= LSEQ) continue;
        const float a = sc[j] * inv;
        const float* vrow = qkv + ((size_t)(b * LSEQ + row) * 3 + 2) * CDIM;
        #pragma unroll
        for (int i = 0; i < 16; i++) acc[i] += a * vrow[lane + 32 * i];
    }

    __nv_bfloat16* hrow = att_hi + (size_t)gwarp * CDIM;
    __nv_bfloat16* lrow = att_lo + (size_t)gwarp * CDIM;
    #pragma unroll
    for (int i = 0; i < 16; i++) {
        const float v = acc[i];
        __nv_bfloat16 h = __float2bfloat16(v);
        hrow[lane + 32 * i] = h;
        lrow[lane + 32 * i] = __float2bfloat16(v - __bfloat162float(h));
    }
}

// ---------------------------------------------------------------------------
extern "C" void kernel_launch(void* const* d_in, const int* in_sizes, int n_in,
                              void* d_out, int out_size)
{
    const float* x       = (const float*)d_in[0];
    const float* w_qkv   = (const float*)d_in[1];
    const float* w_width = (const float*)d_in[2];
    const float* b_width = (const float*)d_in[3];
    const float* w_out   = (const float*)d_in[4];
    float* out = (float*)d_out;

    float* qkv;          cudaGetSymbolAddress((void**)&qkv,  g_qkv);
    __nv_bfloat16* xhi;  cudaGetSymbolAddress((void**)&xhi,  g_xhi);
    __nv_bfloat16* xlo;  cudaGetSymbolAddress((void**)&xlo,  g_xlo);
    __nv_bfloat16* ahi;  cudaGetSymbolAddress((void**)&ahi,  g_ahi);
    __nv_bfloat16* alo;  cudaGetSymbolAddress((void**)&alo,  g_alo);
    __nv_bfloat16* wqhi; cudaGetSymbolAddress((void**)&wqhi, g_wqhi);
    __nv_bfloat16* wqlo; cudaGetSymbolAddress((void**)&wqlo, g_wqlo);
    __nv_bfloat16* wohi; cudaGetSymbolAddress((void**)&wohi, g_wohi);
    __nv_bfloat16* wolo; cudaGetSymbolAddress((void**)&wolo, g_wolo);

    cudaFuncSetAttribute(gemm_mma, cudaFuncAttributeMaxDynamicSharedMemorySize, GEMM_SMEM);

    // 0) input splits
    split_kernel<<<(NTOK * CDIM) / (256 * 4), 256>>>(x, xhi, xlo);
    {
        dim3 g(3 * CDIM / 32, CDIM / 32);
        wsplit_kernel<<<g, dim3(32, 8)>>>(w_qkv, wqhi, wqlo, CDIM, 3 * CDIM);
    }
    {
        dim3 g(CDIM / 32, CDIM / 32);
        wsplit_kernel<<<g, dim3(32, 8)>>>(w_out, wohi, wolo, CDIM, CDIM);
    }

    // 1) qkv = x @ w_qkv   (M=16384, N=1536, K=512)
    {
        dim3 grid(3 * CDIM / 128, NTOK / 128);
        gemm_mma<<<grid, 256, GEMM_SMEM>>>(xhi, xlo, wqhi, wqlo, qkv, 3 * CDIM);
    }

    // 2) fused windowed attention -> att_hi/att_lo (bf16 split)
    attn_kernel<<<NTOK / 8, 256>>>(x, w_width, b_width, ahi, alo);

    // 3) out = att @ w_out  (M=16384, N=512, K=512)
    {
        dim3 grid(CDIM / 128, NTOK / 128);
        gemm_mma<<<grid, 256, GEMM_SMEM>>>(ahi, alo, wohi, wolo, out, CDIM);
    }
}

// round 6
// speedup vs baseline: 2.1242x; 1.2458x over previous
#include <cuda_runtime.h>
#include <cuda_fp16.h>
#include <cstdint>

// Problem constants
#define BDIM 2
#define LSEQ 8192
#define CDIM 512
#define KWIN 17
#define HALFK 8
#define NTOK (BDIM * LSEQ)      // 16384

// ---------------------------------------------------------------------------
// Scratch (__device__ globals; no cudaMalloc allowed)
// ---------------------------------------------------------------------------
__device__ float   g_qkv[(size_t)NTOK * 3 * CDIM];     // 96 MB fp32
__device__ __half  g_xhi[(size_t)NTOK * CDIM];
__device__ __half  g_xlo[(size_t)NTOK * CDIM];
__device__ __half  g_ahi[(size_t)NTOK * CDIM];
__device__ __half  g_alo[(size_t)NTOK * CDIM];
__device__ __half  g_wqhi[(size_t)3 * CDIM * CDIM];    // [1536][512] = w_qkv^T
__device__ __half  g_wqlo[(size_t)3 * CDIM * CDIM];    // (unused by 2-term, kept for wsplit)
__device__ __half  g_wohi[(size_t)CDIM * CDIM];        // [512][512]  = w_out^T
__device__ __half  g_wolo[(size_t)CDIM * CDIM];

// ---------------------------------------------------------------------------
// helpers
// ---------------------------------------------------------------------------
__device__ __forceinline__ uint32_t smem_u32(const void* p) {
    uint32_t a;
    asm("{ .reg .u64 t; cvta.to.shared.u64 t, %1; cvt.u32.u64 %0, t; }" : "=r"(a) : "l"(p));
    return a;
}
__device__ __forceinline__ void cp16(uint32_t dst, const void* src) {
    asm volatile("cp.async.cg.shared.global [%0], [%1], 16;" :: "r"(dst), "l"(src));
}
__device__ __forceinline__ void ldsm_x4(uint32_t* r, uint32_t addr) {
    asm volatile("ldmatrix.sync.aligned.m8n8.x4.shared.b16 {%0,%1,%2,%3}, [%4];"
                 : "=r"(r[0]), "=r"(r[1]), "=r"(r[2]), "=r"(r[3]) : "r"(addr));
}
__device__ __forceinline__ void ldsm_x2(uint32_t* r, uint32_t addr) {
    asm volatile("ldmatrix.sync.aligned.m8n8.x2.shared.b16 {%0,%1}, [%2];"
                 : "=r"(r[0]), "=r"(r[1]) : "r"(addr));
}
__device__ __forceinline__ void mma_f16(float* c, const uint32_t* a, const uint32_t* b) {
    asm volatile(
        "mma.sync.aligned.m16n8k16.row.col.f32.f16.f16.f32 "
        "{%0,%1,%2,%3}, {%4,%5,%6,%7}, {%8,%9}, {%0,%1,%2,%3};"
        : "+f"(c[0]), "+f"(c[1]), "+f"(c[2]), "+f"(c[3])
        : "r"(a[0]), "r"(a[1]), "r"(a[2]), "r"(a[3]), "r"(b[0]), "r"(b[1]));
}
#define CPWAIT(N) asm volatile("cp.async.wait_group %0;" :: "n"(N))

// ---------------------------------------------------------------------------
// Split-fp16 GEMM via mma.sync.
// TERMS=2: D = (Ahi+Alo)@Bhi^T        (err ~ u_fp16 from B truncation)
// TERMS=3: D = Ahi@Bhi + Alo@Bhi + Ahi@Blo  (err ~ u_fp16^2)
// Block 128x128, 8 warps (2x4), warp 64x32, BK=32.
// TERMS=2 -> 3 SMEM mats, 3-stage pipeline; TERMS=3 -> 4 mats, 2-stage.
// 2 CTAs/SM (independent barrier domains). 80B pitch -> conflict-free ldmatrix.
// ---------------------------------------------------------------------------
#define GK       512
#define BK       32
#define NSTG     (GK / BK)          // 16
#define PITCH    80
#define A_SZ     (128 * PITCH)      // 10240

template <int TERMS>
__global__ __launch_bounds__(256, 2) void gemm_mma(
    const __half* __restrict__ Ahi, const __half* __restrict__ Alo,
    const __half* __restrict__ Bhi, const __half* __restrict__ Blo,
    float* __restrict__ C, int Ntot)
{
    constexpr int NMAT = TERMS + 1;           // Ahi, Alo, Bhi (+Blo)
    constexpr int NBUF = (TERMS == 2) ? 3 : 2;
    constexpr uint32_t STG = NMAT * A_SZ;

    extern __shared__ char smem[];
    const uint32_t sb = smem_u32(smem);
    const int tid  = threadIdx.x;
    const int wid  = tid >> 5;
    const int lane = tid & 31;
    const int bm = blockIdx.y * 128;
    const int bn = blockIdx.x * 128;
    const int warp_m = (wid >> 2) * 64;
    const int warp_n = (wid & 3) * 32;

    const int lrow = tid >> 2;
    const int lc16 = (tid & 3) * 16;
    auto load_stage = [&](int s, int b) {
        const int k0 = s * BK;
        const uint32_t buf = sb + (uint32_t)b * STG;
        #pragma unroll
        for (int r = 0; r < 2; r++) {
            const int row = lrow + r * 64;
            const uint32_t off = (uint32_t)(row * PITCH + lc16);
            const size_t ga = (size_t)(bm + row) * GK + k0 + (lc16 >> 1);
            const size_t gb = (size_t)(bn + row) * GK + k0 + (lc16 >> 1);
            cp16(buf + off,            Ahi + ga);
            cp16(buf + A_SZ + off,     Alo + ga);
            cp16(buf + 2 * A_SZ + off, Bhi + gb);
            if (TERMS == 3) cp16(buf + 3 * A_SZ + off, Blo + gb);
        }
        asm volatile("cp.async.commit_group;" ::: "memory");
    };

    float acc[4][4][4];
    #pragma unroll
    for (int mi = 0; mi < 4; mi++)
        #pragma unroll
        for (int ni = 0; ni < 4; ni++)
            #pragma unroll
            for (int f = 0; f < 4; f++) acc[mi][ni][f] = 0.f;

    const uint32_t aLane = (uint32_t)((warp_m + (lane & 15)) * PITCH + ((lane >> 4) & 1) * 16);
    const uint32_t bLane = (uint32_t)((warp_n + (lane & 7)) * PITCH + ((lane >> 3) & 1) * 16);

    #pragma unroll
    for (int p = 0; p < NBUF; p++) load_stage(p, p);

    for (int s = 0; s < NSTG; s++) {
        const int b = s % NBUF;
        if (s <= NSTG - NBUF)                      { CPWAIT(NBUF - 1); }
        else if (NBUF == 3 && s == NSTG - 2)       { CPWAIT(1); }
        else                                       { CPWAIT(0); }
        __syncthreads();

        const uint32_t buf = sb + (uint32_t)b * STG;
        #pragma unroll
        for (int kk = 0; kk < 2; kk++) {
            const uint32_t ko = (uint32_t)(kk * 32);
            uint32_t ah[4][4], al[4][4], bh[4][2], bl[4][2];
            #pragma unroll
            for (int mi = 0; mi < 4; mi++)
                ldsm_x4(ah[mi], buf + aLane + (uint32_t)(mi * 16 * PITCH) + ko);
            #pragma unroll
            for (int mi = 0; mi < 4; mi++)
                ldsm_x4(al[mi], buf + A_SZ + aLane + (uint32_t)(mi * 16 * PITCH) + ko);
            #pragma unroll
            for (int ni = 0; ni < 4; ni++)
                ldsm_x2(bh[ni], buf + 2 * A_SZ + bLane + (uint32_t)(ni * 8 * PITCH) + ko);
            if (TERMS == 3) {
                #pragma unroll
                for (int ni = 0; ni < 4; ni++)
                    ldsm_x2(bl[ni], buf + 3 * A_SZ + bLane + (uint32_t)(ni * 8 * PITCH) + ko);
            }
            #pragma unroll
            for (int mi = 0; mi < 4; mi++)
                #pragma unroll
                for (int ni = 0; ni < 4; ni++) {
                    mma_f16(acc[mi][ni], ah[mi], bh[ni]);
                    mma_f16(acc[mi][ni], al[mi], bh[ni]);
                    if (TERMS == 3) mma_f16(acc[mi][ni], ah[mi], bl[ni]);
                }
        }
        __syncthreads();
        if (s + NBUF < NSTG) load_stage(s + NBUF, b);
    }

    const int er = lane >> 2;
    const int ec = (lane & 3) * 2;
    #pragma unroll
    for (int mi = 0; mi < 4; mi++) {
        #pragma unroll
        for (int ni = 0; ni < 4; ni++) {
            float* p0 = C + (size_t)(bm + warp_m + mi * 16 + er) * Ntot + bn + warp_n + ni * 8 + ec;
            *(float2*)p0                      = make_float2(acc[mi][ni][0], acc[mi][ni][1]);
            *(float2*)(p0 + (size_t)8 * Ntot) = make_float2(acc[mi][ni][2], acc[mi][ni][3]);
        }
    }
}

// ---------------------------------------------------------------------------
// fp32 -> (hi, lo) fp16 split, elementwise
// ---------------------------------------------------------------------------
__global__ __launch_bounds__(256) void split_kernel(const float* __restrict__ src,
                                                    __half* __restrict__ hi,
                                                    __half* __restrict__ lo)
{
    const size_t i = ((size_t)blockIdx.x * blockDim.x + threadIdx.x) * 4;
    float4 v = *(const float4*)(src + i);
    __half h0 = __float2half(v.x), h1 = __float2half(v.y);
    __half h2 = __float2half(v.z), h3 = __float2half(v.w);
    __half l0 = __float2half(v.x - __half2float(h0));
    __half l1 = __float2half(v.y - __half2float(h1));
    __half l2 = __float2half(v.z - __half2float(h2));
    __half l3 = __float2half(v.w - __half2float(h3));
    *(__half2*)(hi + i)     = __halves2half2(h0, h1);
    *(__half2*)(hi + i + 2) = __halves2half2(h2, h3);
    *(__half2*)(lo + i)     = __halves2half2(l0, l1);
    *(__half2*)(lo + i + 2) = __halves2half2(l2, l3);
}

// ---------------------------------------------------------------------------
// weight transpose + split: w[K,N] fp32 -> hiT/loT [N,K] fp16
// ---------------------------------------------------------------------------
__global__ __launch_bounds__(256) void wsplit_kernel(const float* __restrict__ w,
                                                     __half* __restrict__ hiT,
                                                     __half* __restrict__ loT,
                                                     int K, int N)
{
    __shared__ float t[32][33];
    const int k0 = blockIdx.y * 32;
    const int n0 = blockIdx.x * 32;
    const int tx = threadIdx.x, ty = threadIdx.y;
    #pragma unroll
    for (int i = ty; i < 32; i += 8)
        t[i][tx] = w[(size_t)(k0 + i) * N + n0 + tx];
    __syncthreads();
    #pragma unroll
    for (int i = ty; i < 32; i += 8) {
        const float v = t[tx][i];
        __half h = __float2half(v);
        __half l = __float2half(v - __half2float(h));
        hiT[(size_t)(n0 + i) * K + k0 + tx] = h;
        loT[(size_t)(n0 + i) * K + k0 + tx] = l;
    }
}

// ---------------------------------------------------------------------------
// Warp-per-token windowed attention (float4 vectorized); fp16 hi/lo output
// ---------------------------------------------------------------------------
__global__ __launch_bounds__(256) void attn_kernel(const float* __restrict__ x,
                                                   const float* __restrict__ w_width,
                                                   const float* __restrict__ b_width,
                                                   __half* __restrict__ att_hi,
                                                   __half* __restrict__ att_lo)
{
    const int gwarp = (blockIdx.x * blockDim.x + threadIdx.x) >> 5;
    const int lane = threadIdx.x & 31;
    if (gwarp >= NTOK) return;

    const int b = gwarp >> 13;
    const int l = gwarp & (LSEQ - 1);

    const float* qkv = g_qkv;
    const float4* qrow4 = (const float4*)(qkv + (size_t)gwarp * 3 * CDIM);

    float4 q4[4];
    #pragma unroll
    for (int i = 0; i < 4; i++) q4[i] = qrow4[lane + 32 * i];

    // width = sigmoid(x . w_width + b) * 16 + 1
    const float4* x4 = (const float4*)(x + (size_t)gwarp * CDIM);
    const float4* w4 = (const float4*)w_width;
    float wsum = 0.f;
    #pragma unroll
    for (int i = 0; i < 4; i++) {
        const float4 xv = x4[lane + 32 * i];
        const float4 wv = w4[lane + 32 * i];
        wsum += xv.x * wv.x + xv.y * wv.y + xv.z * wv.z + xv.w * wv.w;
    }
    #pragma unroll
    for (int o = 16; o > 0; o >>= 1) wsum += __shfl_xor_sync(0xffffffffu, wsum, o);
    const float width = 1.f / (1.f + expf(-(wsum + b_width[0]))) * (float)(KWIN - 1) + 1.f;

    float sc[KWIN];
    #pragma unroll
    for (int j = 0; j < KWIN; j++) {
        const int row = l + j - HALFK;
        float s = 0.f;
        if (row >= 0 && row < LSEQ) {
            const float4* k4 = (const float4*)(qkv + ((size_t)(b * LSEQ + row) * 3 + 1) * CDIM);
            #pragma unroll
            for (int i = 0; i < 4; i++) {
                const float4 kv = k4[lane + 32 * i];
                s += q4[i].x * kv.x + q4[i].y * kv.y + q4[i].z * kv.z + q4[i].w * kv.w;
            }
        }
        #pragma unroll
        for (int o = 16; o > 0; o >>= 1) s += __shfl_xor_sync(0xffffffffu, s, o);
        sc[j] = s;
    }

    const float scale = 0.044194173824159216f;
    float mx = -1e30f;
    #pragma unroll
    for (int j = 0; j < KWIN; j++) {
        const float rel = fabsf((float)j - (float)HALFK);
        const float m = 1.f / (1.f + expf(-(width - rel) * 5.f));
        sc[j] = sc[j] * scale - (1.f - m) * 10000.f;
        mx = fmaxf(mx, sc[j]);
    }
    float denom = 0.f;
    #pragma unroll
    for (int j = 0; j < KWIN; j++) {
        sc[j] = expf(sc[j] - mx);
        denom += sc[j];
    }
    const float inv = 1.f / denom;

    float4 acc4[4];
    const float4* vs4 = (const float4*)(qkv + ((size_t)gwarp * 3 + 2) * CDIM);
    #pragma unroll
    for (int i = 0; i < 4; i++) acc4[i] = vs4[lane + 32 * i];

    #pragma unroll
    for (int j = 0; j < KWIN; j++) {
        const int row = l + j - HALFK;
        if (row < 0 || row >= LSEQ) continue;
        const float a = sc[j] * inv;
        const float4* v4 = (const float4*)(qkv + ((size_t)(b * LSEQ + row) * 3 + 2) * CDIM);
        #pragma unroll
        for (int i = 0; i < 4; i++) {
            const float4 vv = v4[lane + 32 * i];
            acc4[i].x += a * vv.x;
            acc4[i].y += a * vv.y;
            acc4[i].z += a * vv.z;
            acc4[i].w += a * vv.w;
        }
    }

    __half* hrow = att_hi + (size_t)gwarp * CDIM;
    __half* lrow = att_lo + (size_t)gwarp * CDIM;
    #pragma unroll
    for (int i = 0; i < 4; i++) {
        const int c = 4 * lane + 128 * i;
        __half h0 = __float2half(acc4[i].x), h1 = __float2half(acc4[i].y);
        __half h2 = __float2half(acc4[i].z), h3 = __float2half(acc4[i].w);
        *(__half2*)(hrow + c)     = __halves2half2(h0, h1);
        *(__half2*)(hrow + c + 2) = __halves2half2(h2, h3);
        __half l0 = __float2half(acc4[i].x - __half2float(h0));
        __half l1 = __float2half(acc4[i].y - __half2float(h1));
        __half l2 = __float2half(acc4[i].z - __half2float(h2));
        __half l3 = __float2half(acc4[i].w - __half2float(h3));
        *(__half2*)(lrow + c)     = __halves2half2(l0, l1);
        *(__half2*)(lrow + c + 2) = __halves2half2(l2, l3);
    }
}

// ---------------------------------------------------------------------------
extern "C" void kernel_launch(void* const* d_in, const int* in_sizes, int n_in,
                              void* d_out, int out_size)
{
    const float* x       = (const float*)d_in[0];
    const float* w_qkv   = (const float*)d_in[1];
    const float* w_width = (const float*)d_in[2];
    const float* b_width = (const float*)d_in[3];
    const float* w_out   = (const float*)d_in[4];
    float* out = (float*)d_out;

    float* qkv;   cudaGetSymbolAddress((void**)&qkv,  g_qkv);
    __half* xhi;  cudaGetSymbolAddress((void**)&xhi,  g_xhi);
    __half* xlo;  cudaGetSymbolAddress((void**)&xlo,  g_xlo);
    __half* ahi;  cudaGetSymbolAddress((void**)&ahi,  g_ahi);
    __half* alo;  cudaGetSymbolAddress((void**)&alo,  g_alo);
    __half* wqhi; cudaGetSymbolAddress((void**)&wqhi, g_wqhi);
    __half* wqlo; cudaGetSymbolAddress((void**)&wqlo, g_wqlo);
    __half* wohi; cudaGetSymbolAddress((void**)&wohi, g_wohi);
    __half* wolo; cudaGetSymbolAddress((void**)&wolo, g_wolo);

    const int SMEM2 = 3 * 3 * A_SZ;   // 3 mats, 3 stages = 92160
    const int SMEM3 = 2 * 4 * A_SZ;   // 4 mats, 2 stages = 81920
    cudaFuncSetAttribute(gemm_mma<2>, cudaFuncAttributeMaxDynamicSharedMemorySize, SMEM2);
    cudaFuncSetAttribute(gemm_mma<3>, cudaFuncAttributeMaxDynamicSharedMemorySize, SMEM3);

    // 0) input splits
    split_kernel<<<(NTOK * CDIM) / (256 * 4), 256>>>(x, xhi, xlo);
    {
        dim3 g(3 * CDIM / 32, CDIM / 32);
        wsplit_kernel<<<g, dim3(32, 8)>>>(w_qkv, wqhi, wqlo, CDIM, 3 * CDIM);
    }
    {
        dim3 g(CDIM / 32, CDIM / 32);
        wsplit_kernel<<<g, dim3(32, 8)>>>(w_out, wohi, wolo, CDIM, CDIM);
    }

    // 1) qkv = x @ w_qkv   (2-term fp16 split: err ~2.4e-4)
    {
        dim3 grid(3 * CDIM / 128, NTOK / 128);
        gemm_mma<2><<<grid, 256, SMEM2>>>(xhi, xlo, wqhi, wqlo, qkv, 3 * CDIM);
    }

    // 2) fused windowed attention -> att hi/lo (fp16 split)
    attn_kernel<<<NTOK / 8, 256>>>(x, w_width, b_width, ahi, alo);

    // 3) out = att @ w_out  (3-term fp16 split: err ~u^2, keeps total margin)
    {
        dim3 grid(CDIM / 128, NTOK / 128);
        gemm_mma<3><<<grid, 256, SMEM3>>>(ahi, alo, wohi, wolo, out, CDIM);
    }
}

// round 7
// speedup vs baseline: 2.4908x; 1.1725x over previous
#include <cuda_runtime.h>
#include <cuda_fp16.h>
#include <cstdint>

// Problem constants
#define BDIM 2
#define LSEQ 8192
#define CDIM 512
#define KWIN 17
#define HALFK 8
#define NTOK (BDIM * LSEQ)      // 16384

// ---------------------------------------------------------------------------
// Scratch (__device__ globals; no cudaMalloc allowed)
// ---------------------------------------------------------------------------
__device__ float   g_qkv[(size_t)NTOK * 3 * CDIM];     // 96 MB fp32
__device__ __half  g_xhi[(size_t)NTOK * CDIM];
__device__ __half  g_xlo[(size_t)NTOK * CDIM];
__device__ __half  g_ahi[(size_t)NTOK * CDIM];
__device__ __half  g_alo[(size_t)NTOK * CDIM];
__device__ __half  g_wqhi[(size_t)3 * CDIM * CDIM];    // [1536][512] = w_qkv^T hi
__device__ __half  g_wohi[(size_t)CDIM * CDIM];        // [512][512]  = w_out^T hi

// ---------------------------------------------------------------------------
// helpers
// ---------------------------------------------------------------------------
__device__ __forceinline__ uint32_t smem_u32(const void* p) {
    uint32_t a;
    asm("{ .reg .u64 t; cvta.to.shared.u64 t, %1; cvt.u32.u64 %0, t; }" : "=r"(a) : "l"(p));
    return a;
}
__device__ __forceinline__ void cp16(uint32_t dst, const void* src) {
    asm volatile("cp.async.cg.shared.global [%0], [%1], 16;" :: "r"(dst), "l"(src));
}
__device__ __forceinline__ void ldsm_x4(uint32_t* r, uint32_t addr) {
    asm volatile("ldmatrix.sync.aligned.m8n8.x4.shared.b16 {%0,%1,%2,%3}, [%4];"
                 : "=r"(r[0]), "=r"(r[1]), "=r"(r[2]), "=r"(r[3]) : "r"(addr));
}
__device__ __forceinline__ void ldsm_x2(uint32_t* r, uint32_t addr) {
    asm volatile("ldmatrix.sync.aligned.m8n8.x2.shared.b16 {%0,%1}, [%2];"
                 : "=r"(r[0]), "=r"(r[1]) : "r"(addr));
}
__device__ __forceinline__ void mma_f16(float* c, const uint32_t* a, const uint32_t* b) {
    asm volatile(
        "mma.sync.aligned.m16n8k16.row.col.f32.f16.f16.f32 "
        "{%0,%1,%2,%3}, {%4,%5,%6,%7}, {%8,%9}, {%0,%1,%2,%3};"
        : "+f"(c[0]), "+f"(c[1]), "+f"(c[2]), "+f"(c[3])
        : "r"(a[0]), "r"(a[1]), "r"(a[2]), "r"(a[3]), "r"(b[0]), "r"(b[1]));
}
#define CPWAIT(N) asm volatile("cp.async.wait_group %0;" :: "n"(N))

// ---------------------------------------------------------------------------
// 2-term split-fp16 GEMM:  C = (Ahi + Alo) @ Bhi^T   (fp32 accum)
// Block 128x128, 8 warps (2x4), warp 64x32.  BK=64 stages (8 total), double
// buffered cp.async; 2 CTAs/SM.  PITCH=144 -> conflict-free ldmatrix
// (row stride 36 words == 4 mod 32 banks; 8 rows span all banks).
// ---------------------------------------------------------------------------
#define GK       512
#define BK       64
#define NSTG     (GK / BK)          // 8
#define PITCH    144                // 128B data + 16B pad
#define A_SZ     (128 * PITCH)      // 18432
#define STG_SZ   (3 * A_SZ)         // Ahi | Alo | Bhi = 55296
#define GEMM_SMEM (2 * STG_SZ)      // 110592

__global__ __launch_bounds__(256, 2) void gemm_mma(
    const __half* __restrict__ Ahi, const __half* __restrict__ Alo,
    const __half* __restrict__ Bhi,
    float* __restrict__ C, int Ntot)
{
    extern __shared__ char smem[];
    const uint32_t sb = smem_u32(smem);
    const int tid  = threadIdx.x;
    const int wid  = tid >> 5;
    const int lane = tid & 31;
    const int bm = blockIdx.y * 128;
    const int bn = blockIdx.x * 128;
    const int warp_m = (wid >> 2) * 64;
    const int warp_n = (wid & 3) * 32;

    // ---- loader: 128 rows x 8 chunks(16B) per matrix, 256 threads ----
    const int lrow = tid >> 1;                   // i = tid + 256*r -> row = i>>3
    auto load_stage = [&](int s, int b) {
        const int k0 = s * BK;
        const uint32_t buf = sb + (uint32_t)b * STG_SZ;
        #pragma unroll
        for (int r = 0; r < 4; r++) {
            const int i   = tid + 256 * r;
            const int row = i >> 3;
            const int c16 = (i & 7) * 16;
            const uint32_t off = (uint32_t)(row * PITCH + c16);
            const size_t ga = (size_t)(bm + row) * GK + k0 + (c16 >> 1);
            const size_t gb = (size_t)(bn + row) * GK + k0 + (c16 >> 1);
            cp16(buf + off,            Ahi + ga);
            cp16(buf + A_SZ + off,     Alo + ga);
            cp16(buf + 2 * A_SZ + off, Bhi + gb);
        }
        asm volatile("cp.async.commit_group;" ::: "memory");
    };

    float acc[4][4][4];
    #pragma unroll
    for (int mi = 0; mi < 4; mi++)
        #pragma unroll
        for (int ni = 0; ni < 4; ni++)
            #pragma unroll
            for (int f = 0; f < 4; f++) acc[mi][ni][f] = 0.f;

    const uint32_t aLane = (uint32_t)((warp_m + (lane & 15)) * PITCH + ((lane >> 4) & 1) * 16);
    const uint32_t bLane = (uint32_t)((warp_n + (lane & 7)) * PITCH + ((lane >> 3) & 1) * 16);

    load_stage(0, 0);
    load_stage(1, 1);

    for (int s = 0; s < NSTG; s++) {
        const int b = s & 1;
        if (s + 1 < NSTG) CPWAIT(1);
        else              CPWAIT(0);
        __syncthreads();

        const uint32_t buf = sb + (uint32_t)b * STG_SZ;
        #pragma unroll
        for (int kk = 0; kk < 4; kk++) {                 // four k16 steps per stage
            const uint32_t ko = (uint32_t)(kk * 32);
            uint32_t ah[4][4], al[4][4], bh[4][2];
            #pragma unroll
            for (int mi = 0; mi < 4; mi++)
                ldsm_x4(ah[mi], buf + aLane + (uint32_t)(mi * 16 * PITCH) + ko);
            #pragma unroll
            for (int mi = 0; mi < 4; mi++)
                ldsm_x4(al[mi], buf + A_SZ + aLane + (uint32_t)(mi * 16 * PITCH) + ko);
            #pragma unroll
            for (int ni = 0; ni < 4; ni++)
                ldsm_x2(bh[ni], buf + 2 * A_SZ + bLane + (uint32_t)(ni * 8 * PITCH) + ko);
            #pragma unroll
            for (int mi = 0; mi < 4; mi++)
                #pragma unroll
                for (int ni = 0; ni < 4; ni++) {
                    mma_f16(acc[mi][ni], ah[mi], bh[ni]);
                    mma_f16(acc[mi][ni], al[mi], bh[ni]);
                }
        }
        __syncthreads();
        if (s + 2 < NSTG) load_stage(s + 2, b);
    }

    const int er = lane >> 2;
    const int ec = (lane & 3) * 2;
    #pragma unroll
    for (int mi = 0; mi < 4; mi++) {
        #pragma unroll
        for (int ni = 0; ni < 4; ni++) {
            float* p0 = C + (size_t)(bm + warp_m + mi * 16 + er) * Ntot + bn + warp_n + ni * 8 + ec;
            *(float2*)p0                      = make_float2(acc[mi][ni][0], acc[mi][ni][1]);
            *(float2*)(p0 + (size_t)8 * Ntot) = make_float2(acc[mi][ni][2], acc[mi][ni][3]);
        }
    }
}

// ---------------------------------------------------------------------------
// fp32 -> (hi, lo) fp16 split, elementwise
// ---------------------------------------------------------------------------
__global__ __launch_bounds__(256) void split_kernel(const float* __restrict__ src,
                                                    __half* __restrict__ hi,
                                                    __half* __restrict__ lo)
{
    const size_t i = ((size_t)blockIdx.x * blockDim.x + threadIdx.x) * 4;
    float4 v = *(const float4*)(src + i);
    __half h0 = __float2half(v.x), h1 = __float2half(v.y);
    __half h2 = __float2half(v.z), h3 = __float2half(v.w);
    __half l0 = __float2half(v.x - __half2float(h0));
    __half l1 = __float2half(v.y - __half2float(h1));
    __half l2 = __float2half(v.z - __half2float(h2));
    __half l3 = __float2half(v.w - __half2float(h3));
    *(__half2*)(hi + i)     = __halves2half2(h0, h1);
    *(__half2*)(hi + i + 2) = __halves2half2(h2, h3);
    *(__half2*)(lo + i)     = __halves2half2(l0, l1);
    *(__half2*)(lo + i + 2) = __halves2half2(l2, l3);
}

// ---------------------------------------------------------------------------
// weight transpose (hi only): w[K,N] fp32 -> hiT [N,K] fp16
// ---------------------------------------------------------------------------
__global__ __launch_bounds__(256) void wsplit_kernel(const float* __restrict__ w,
                                                     __half* __restrict__ hiT,
                                                     int K, int N)
{
    __shared__ float t[32][33];
    const int k0 = blockIdx.y * 32;
    const int n0 = blockIdx.x * 32;
    const int tx = threadIdx.x, ty = threadIdx.y;
    #pragma unroll
    for (int i = ty; i < 32; i += 8)
        t[i][tx] = w[(size_t)(k0 + i) * N + n0 + tx];
    __syncthreads();
    #pragma unroll
    for (int i = ty; i < 32; i += 8)
        hiT[(size_t)(n0 + i) * K + k0 + tx] = __float2half(t[tx][i]);
}

// ---------------------------------------------------------------------------
// Warp-per-token windowed attention (float4 vectorized); fp16 hi/lo output
// ---------------------------------------------------------------------------
__global__ __launch_bounds__(256) void attn_kernel(const float* __restrict__ x,
                                                   const float* __restrict__ w_width,
                                                   const float* __restrict__ b_width,
                                                   __half* __restrict__ att_hi,
                                                   __half* __restrict__ att_lo)
{
    const int gwarp = (blockIdx.x * blockDim.x + threadIdx.x) >> 5;
    const int lane = threadIdx.x & 31;
    if (gwarp >= NTOK) return;

    const int b = gwarp >> 13;
    const int l = gwarp & (LSEQ - 1);

    const float* qkv = g_qkv;
    const float4* qrow4 = (const float4*)(qkv + (size_t)gwarp * 3 * CDIM);

    float4 q4[4];
    #pragma unroll
    for (int i = 0; i < 4; i++) q4[i] = qrow4[lane + 32 * i];

    const float4* x4 = (const float4*)(x + (size_t)gwarp * CDIM);
    const float4* w4 = (const float4*)w_width;
    float wsum = 0.f;
    #pragma unroll
    for (int i = 0; i < 4; i++) {
        const float4 xv = x4[lane + 32 * i];
        const float4 wv = w4[lane + 32 * i];
        wsum += xv.x * wv.x + xv.y * wv.y + xv.z * wv.z + xv.w * wv.w;
    }
    #pragma unroll
    for (int o = 16; o > 0; o >>= 1) wsum += __shfl_xor_sync(0xffffffffu, wsum, o);
    const float width = 1.f / (1.f + expf(-(wsum + b_width[0]))) * (float)(KWIN - 1) + 1.f;

    float sc[KWIN];
    #pragma unroll
    for (int j = 0; j < KWIN; j++) {
        const int row = l + j - HALFK;
        float s = 0.f;
        if (row >= 0 && row < LSEQ) {
            const float4* k4 = (const float4*)(qkv + ((size_t)(b * LSEQ + row) * 3 + 1) * CDIM);
            #pragma unroll
            for (int i = 0; i < 4; i++) {
                const float4 kv = k4[lane + 32 * i];
                s += q4[i].x * kv.x + q4[i].y * kv.y + q4[i].z * kv.z + q4[i].w * kv.w;
            }
        }
        #pragma unroll
        for (int o = 16; o > 0; o >>= 1) s += __shfl_xor_sync(0xffffffffu, s, o);
        sc[j] = s;
    }

    const float scale = 0.044194173824159216f;
    float mx = -1e30f;
    #pragma unroll
    for (int j = 0; j < KWIN; j++) {
        const float rel = fabsf((float)j - (float)HALFK);
        const float m = 1.f / (1.f + expf(-(width - rel) * 5.f));
        sc[j] = sc[j] * scale - (1.f - m) * 10000.f;
        mx = fmaxf(mx, sc[j]);
    }
    float denom = 0.f;
    #pragma unroll
    for (int j = 0; j < KWIN; j++) {
        sc[j] = expf(sc[j] - mx);
        denom += sc[j];
    }
    const float inv = 1.f / denom;

    float4 acc4[4];
    const float4* vs4 = (const float4*)(qkv + ((size_t)gwarp * 3 + 2) * CDIM);
    #pragma unroll
    for (int i = 0; i < 4; i++) acc4[i] = vs4[lane + 32 * i];

    #pragma unroll
    for (int j = 0; j < KWIN; j++) {
        const int row = l + j - HALFK;
        if (row < 0 || row >= LSEQ) continue;
        const float a = sc[j] * inv;
        const float4* v4 = (const float4*)(qkv + ((size_t)(b * LSEQ + row) * 3 + 2) * CDIM);
        #pragma unroll
        for (int i = 0; i < 4; i++) {
            const float4 vv = v4[lane + 32 * i];
            acc4[i].x += a * vv.x;
            acc4[i].y += a * vv.y;
            acc4[i].z += a * vv.z;
            acc4[i].w += a * vv.w;
        }
    }

    __half* hrow = att_hi + (size_t)gwarp * CDIM;
    __half* lrow = att_lo + (size_t)gwarp * CDIM;
    #pragma unroll
    for (int i = 0; i < 4; i++) {
        const int c = 4 * lane + 128 * i;
        __half h0 = __float2half(acc4[i].x), h1 = __float2half(acc4[i].y);
        __half h2 = __float2half(acc4[i].z), h3 = __float2half(acc4[i].w);
        *(__half2*)(hrow + c)     = __halves2half2(h0, h1);
        *(__half2*)(hrow + c + 2) = __halves2half2(h2, h3);
        __half l0 = __float2half(acc4[i].x - __half2float(h0));
        __half l1 = __float2half(acc4[i].y - __half2float(h1));
        __half l2 = __float2half(acc4[i].z - __half2float(h2));
        __half l3 = __float2half(acc4[i].w - __half2float(h3));
        *(__half2*)(lrow + c)     = __halves2half2(l0, l1);
        *(__half2*)(lrow + c + 2) = __halves2half2(l2, l3);
    }
}

// ---------------------------------------------------------------------------
extern "C" void kernel_launch(void* const* d_in, const int* in_sizes, int n_in,
                              void* d_out, int out_size)
{
    const float* x       = (const float*)d_in[0];
    const float* w_qkv   = (const float*)d_in[1];
    const float* w_width = (const float*)d_in[2];
    const float* b_width = (const float*)d_in[3];
    const float* w_out   = (const float*)d_in[4];
    float* out = (float*)d_out;

    float* qkv;   cudaGetSymbolAddress((void**)&qkv,  g_qkv);
    __half* xhi;  cudaGetSymbolAddress((void**)&xhi,  g_xhi);
    __half* xlo;  cudaGetSymbolAddress((void**)&xlo,  g_xlo);
    __half* ahi;  cudaGetSymbolAddress((void**)&ahi,  g_ahi);
    __half* alo;  cudaGetSymbolAddress((void**)&alo,  g_alo);
    __half* wqhi; cudaGetSymbolAddress((void**)&wqhi, g_wqhi);
    __half* wohi; cudaGetSymbolAddress((void**)&wohi, g_wohi);

    cudaFuncSetAttribute(gemm_mma, cudaFuncAttributeMaxDynamicSharedMemorySize, GEMM_SMEM);

    // 0) input splits
    split_kernel<<<(NTOK * CDIM) / (256 * 4), 256>>>(x, xhi, xlo);
    {
        dim3 g(3 * CDIM / 32, CDIM / 32);
        wsplit_kernel<<<g, dim3(32, 8)>>>(w_qkv, wqhi, CDIM, 3 * CDIM);
    }
    {
        dim3 g(CDIM / 32, CDIM / 32);
        wsplit_kernel<<<g, dim3(32, 8)>>>(w_out, wohi, CDIM, CDIM);
    }

    // 1) qkv = x @ w_qkv   (2-term fp16 split)
    {
        dim3 grid(3 * CDIM / 128, NTOK / 128);
        gemm_mma<<<grid, 256, GEMM_SMEM>>>(xhi, xlo, wqhi, qkv, 3 * CDIM);
    }

    // 2) fused windowed attention -> att hi/lo (fp16 split)
    attn_kernel<<<NTOK / 8, 256>>>(x, w_width, b_width, ahi, alo);

    // 3) out = att @ w_out  (2-term fp16 split)
    {
        dim3 grid(CDIM / 128, NTOK / 128);
        gemm_mma<<<grid, 256, GEMM_SMEM>>>(ahi, alo, wohi, out, CDIM);
    }
}

// round 8
// speedup vs baseline: 2.5925x; 1.0408x over previous
#include <cuda_runtime.h>
#include <cuda_fp16.h>
#include <cstdint>

// Problem constants
#define BDIM 2
#define LSEQ 8192
#define CDIM 512
#define KWIN 17
#define HALFK 8
#define NTOK (BDIM * LSEQ)      // 16384

// ---------------------------------------------------------------------------
// Scratch (__device__ globals; no cudaMalloc allowed)
// ---------------------------------------------------------------------------
__device__ __half  g_qkvh[(size_t)NTOK * 3 * CDIM];    // 48 MB fp16 qkv
__device__ __half  g_xhi[(size_t)NTOK * CDIM];
__device__ __half  g_xlo[(size_t)NTOK * CDIM];
__device__ __half  g_ahi[(size_t)NTOK * CDIM];
__device__ __half  g_alo[(size_t)NTOK * CDIM];
__device__ __half  g_wqhi[(size_t)3 * CDIM * CDIM];    // [1536][512] = w_qkv^T hi
__device__ __half  g_wohi[(size_t)CDIM * CDIM];        // [512][512]  = w_out^T hi

// ---------------------------------------------------------------------------
// helpers
// ---------------------------------------------------------------------------
__device__ __forceinline__ uint32_t smem_u32(const void* p) {
    uint32_t a;
    asm("{ .reg .u64 t; cvta.to.shared.u64 t, %1; cvt.u32.u64 %0, t; }" : "=r"(a) : "l"(p));
    return a;
}
__device__ __forceinline__ void cp16(uint32_t dst, const void* src) {
    asm volatile("cp.async.cg.shared.global [%0], [%1], 16;" :: "r"(dst), "l"(src));
}
__device__ __forceinline__ void ldsm_x4(uint32_t* r, uint32_t addr) {
    asm volatile("ldmatrix.sync.aligned.m8n8.x4.shared.b16 {%0,%1,%2,%3}, [%4];"
                 : "=r"(r[0]), "=r"(r[1]), "=r"(r[2]), "=r"(r[3]) : "r"(addr));
}
__device__ __forceinline__ void ldsm_x2(uint32_t* r, uint32_t addr) {
    asm volatile("ldmatrix.sync.aligned.m8n8.x2.shared.b16 {%0,%1}, [%2];"
                 : "=r"(r[0]), "=r"(r[1]) : "r"(addr));
}
__device__ __forceinline__ void mma_f16(float* c, const uint32_t* a, const uint32_t* b) {
    asm volatile(
        "mma.sync.aligned.m16n8k16.row.col.f32.f16.f16.f32 "
        "{%0,%1,%2,%3}, {%4,%5,%6,%7}, {%8,%9}, {%0,%1,%2,%3};"
        : "+f"(c[0]), "+f"(c[1]), "+f"(c[2]), "+f"(c[3])
        : "r"(a[0]), "r"(a[1]), "r"(a[2]), "r"(a[3]), "r"(b[0]), "r"(b[1]));
}
#define CPWAIT(N) asm volatile("cp.async.wait_group %0;" :: "n"(N))

__device__ __forceinline__ void unpack8(uint4 u, float* f) {
    const __half2* h = (const __half2*)&u;
    #pragma unroll
    for (int t = 0; t < 4; t++) {
        float2 v = __half22float2(h[t]);
        f[2 * t] = v.x;
        f[2 * t + 1] = v.y;
    }
}

// ---------------------------------------------------------------------------
// 2-term split-fp16 GEMM:  C = (Ahi + Alo) @ Bhi^T   (fp32 accum, OutT store)
// Block 128x128, 8 warps (2x4), warp 64x32.  BK=64 stages, double buffered
// cp.async; 2 CTAs/SM.  PITCH=144 -> conflict-free ldmatrix.
// ---------------------------------------------------------------------------
#define GK       512
#define BK       64
#define NSTG     (GK / BK)          // 8
#define PITCH    144
#define A_SZ     (128 * PITCH)      // 18432
#define STG_SZ   (3 * A_SZ)         // 55296
#define GEMM_SMEM (2 * STG_SZ)      // 110592

template <typename OutT>
__global__ __launch_bounds__(256, 2) void gemm_mma(
    const __half* __restrict__ Ahi, const __half* __restrict__ Alo,
    const __half* __restrict__ Bhi,
    OutT* __restrict__ C, int Ntot)
{
    extern __shared__ char smem[];
    const uint32_t sb = smem_u32(smem);
    const int tid  = threadIdx.x;
    const int wid  = tid >> 5;
    const int lane = tid & 31;
    const int bm = blockIdx.y * 128;
    const int bn = blockIdx.x * 128;
    const int warp_m = (wid >> 2) * 64;
    const int warp_n = (wid & 3) * 32;

    auto load_stage = [&](int s, int b) {
        const int k0 = s * BK;
        const uint32_t buf = sb + (uint32_t)b * STG_SZ;
        #pragma unroll
        for (int r = 0; r < 4; r++) {
            const int i   = tid + 256 * r;
            const int row = i >> 3;
            const int c16 = (i & 7) * 16;
            const uint32_t off = (uint32_t)(row * PITCH + c16);
            const size_t ga = (size_t)(bm + row) * GK + k0 + (c16 >> 1);
            const size_t gb = (size_t)(bn + row) * GK + k0 + (c16 >> 1);
            cp16(buf + off,            Ahi + ga);
            cp16(buf + A_SZ + off,     Alo + ga);
            cp16(buf + 2 * A_SZ + off, Bhi + gb);
        }
        asm volatile("cp.async.commit_group;" ::: "memory");
    };

    float acc[4][4][4];
    #pragma unroll
    for (int mi = 0; mi < 4; mi++)
        #pragma unroll
        for (int ni = 0; ni < 4; ni++)
            #pragma unroll
            for (int f = 0; f < 4; f++) acc[mi][ni][f] = 0.f;

    const uint32_t aLane = (uint32_t)((warp_m + (lane & 15)) * PITCH + ((lane >> 4) & 1) * 16);
    const uint32_t bLane = (uint32_t)((warp_n + (lane & 7)) * PITCH + ((lane >> 3) & 1) * 16);

    load_stage(0, 0);
    load_stage(1, 1);

    for (int s = 0; s < NSTG; s++) {
        const int b = s & 1;
        if (s + 1 < NSTG) CPWAIT(1);
        else              CPWAIT(0);
        __syncthreads();

        const uint32_t buf = sb + (uint32_t)b * STG_SZ;
        #pragma unroll
        for (int kk = 0; kk < 4; kk++) {
            const uint32_t ko = (uint32_t)(kk * 32);
            uint32_t ah[4][4], al[4][4], bh[4][2];
            #pragma unroll
            for (int mi = 0; mi < 4; mi++)
                ldsm_x4(ah[mi], buf + aLane + (uint32_t)(mi * 16 * PITCH) + ko);
            #pragma unroll
            for (int mi = 0; mi < 4; mi++)
                ldsm_x4(al[mi], buf + A_SZ + aLane + (uint32_t)(mi * 16 * PITCH) + ko);
            #pragma unroll
            for (int ni = 0; ni < 4; ni++)
                ldsm_x2(bh[ni], buf + 2 * A_SZ + bLane + (uint32_t)(ni * 8 * PITCH) + ko);
            #pragma unroll
            for (int mi = 0; mi < 4; mi++)
                #pragma unroll
                for (int ni = 0; ni < 4; ni++) {
                    mma_f16(acc[mi][ni], ah[mi], bh[ni]);
                    mma_f16(acc[mi][ni], al[mi], bh[ni]);
                }
        }
        __syncthreads();
        if (s + 2 < NSTG) load_stage(s + 2, b);
    }

    const int er = lane >> 2;
    const int ec = (lane & 3) * 2;
    #pragma unroll
    for (int mi = 0; mi < 4; mi++) {
        #pragma unroll
        for (int ni = 0; ni < 4; ni++) {
            OutT* p0 = C + (size_t)(bm + warp_m + mi * 16 + er) * Ntot + bn + warp_n + ni * 8 + ec;
            if constexpr (sizeof(OutT) == 2) {
                *(__half2*)p0 = __floats2half2_rn(acc[mi][ni][0], acc[mi][ni][1]);
                *(__half2*)(p0 + (size_t)8 * Ntot) = __floats2half2_rn(acc[mi][ni][2], acc[mi][ni][3]);
            } else {
                *(float2*)p0                      = make_float2(acc[mi][ni][0], acc[mi][ni][1]);
                *(float2*)(p0 + (size_t)8 * Ntot) = make_float2(acc[mi][ni][2], acc[mi][ni][3]);
            }
        }
    }
}

// ---------------------------------------------------------------------------
// fp32 -> (hi, lo) fp16 split, elementwise
// ---------------------------------------------------------------------------
__global__ __launch_bounds__(256) void split_kernel(const float* __restrict__ src,
                                                    __half* __restrict__ hi,
                                                    __half* __restrict__ lo)
{
    const size_t i = ((size_t)blockIdx.x * blockDim.x + threadIdx.x) * 4;
    float4 v = *(const float4*)(src + i);
    __half h0 = __float2half(v.x), h1 = __float2half(v.y);
    __half h2 = __float2half(v.z), h3 = __float2half(v.w);
    __half l0 = __float2half(v.x - __half2float(h0));
    __half l1 = __float2half(v.y - __half2float(h1));
    __half l2 = __float2half(v.z - __half2float(h2));
    __half l3 = __float2half(v.w - __half2float(h3));
    *(__half2*)(hi + i)     = __halves2half2(h0, h1);
    *(__half2*)(hi + i + 2) = __halves2half2(h2, h3);
    *(__half2*)(lo + i)     = __halves2half2(l0, l1);
    *(__half2*)(lo + i + 2) = __halves2half2(l2, l3);
}

// ---------------------------------------------------------------------------
// weight transpose (hi only): w[K,N] fp32 -> hiT [N,K] fp16
// ---------------------------------------------------------------------------
__global__ __launch_bounds__(256) void wsplit_kernel(const float* __restrict__ w,
                                                     __half* __restrict__ hiT,
                                                     int K, int N)
{
    __shared__ float t[32][33];
    const int k0 = blockIdx.y * 32;
    const int n0 = blockIdx.x * 32;
    const int tx = threadIdx.x, ty = threadIdx.y;
    #pragma unroll
    for (int i = ty; i < 32; i += 8)
        t[i][tx] = w[(size_t)(k0 + i) * N + n0 + tx];
    __syncthreads();
    #pragma unroll
    for (int i = ty; i < 32; i += 8)
        hiT[(size_t)(n0 + i) * K + k0 + tx] = __float2half(t[tx][i]);
}

// ---------------------------------------------------------------------------
// Warp-per-token windowed attention over fp16 qkv; fp16 hi/lo output.
// Per lane: 2 x uint4 (8 halves each) per row -> half the L1 bytes of fp32.
// ---------------------------------------------------------------------------
__global__ __launch_bounds__(256) void attn_kernel(const float* __restrict__ x,
                                                   const float* __restrict__ w_width,
                                                   const float* __restrict__ b_width,
                                                   __half* __restrict__ att_hi,
                                                   __half* __restrict__ att_lo)
{
    const int gwarp = (blockIdx.x * blockDim.x + threadIdx.x) >> 5;
    const int lane = threadIdx.x & 31;
    if (gwarp >= NTOK) return;

    const int b = gwarp >> 13;
    const int l = gwarp & (LSEQ - 1);

    const __half* qkv = g_qkvh;

    // q: 16 halves per lane -> fp32 regs
    float q[16];
    {
        const uint4* q4 = (const uint4*)(qkv + (size_t)gwarp * 3 * CDIM);
        #pragma unroll
        for (int i = 0; i < 2; i++) unpack8(q4[lane + 32 * i], q + 8 * i);
    }

    // width = sigmoid(x . w_width + b) * 16 + 1   (fp32 inputs)
    const float4* x4 = (const float4*)(x + (size_t)gwarp * CDIM);
    const float4* w4 = (const float4*)w_width;
    float wsum = 0.f;
    #pragma unroll
    for (int i = 0; i < 4; i++) {
        const float4 xv = x4[lane + 32 * i];
        const float4 wv = w4[lane + 32 * i];
        wsum += xv.x * wv.x + xv.y * wv.y + xv.z * wv.z + xv.w * wv.w;
    }
    #pragma unroll
    for (int o = 16; o > 0; o >>= 1) wsum += __shfl_xor_sync(0xffffffffu, wsum, o);
    const float width = 1.f / (1.f + expf(-(wsum + b_width[0]))) * (float)(KWIN - 1) + 1.f;

    float sc[KWIN];
    #pragma unroll
    for (int j = 0; j < KWIN; j++) {
        const int row = l + j - HALFK;
        float s = 0.f;
        if (row >= 0 && row < LSEQ) {
            const uint4* k4 = (const uint4*)(qkv + ((size_t)(b * LSEQ + row) * 3 + 1) * CDIM);
            #pragma unroll
            for (int i = 0; i < 2; i++) {
                float kf[8];
                unpack8(k4[lane + 32 * i], kf);
                #pragma unroll
                for (int t = 0; t < 8; t++) s += q[8 * i + t] * kf[t];
            }
        }
        #pragma unroll
        for (int o = 16; o > 0; o >>= 1) s += __shfl_xor_sync(0xffffffffu, s, o);
        sc[j] = s;
    }

    const float scale = 0.044194173824159216f;
    float mx = -1e30f;
    #pragma unroll
    for (int j = 0; j < KWIN; j++) {
        const float rel = fabsf((float)j - (float)HALFK);
        const float m = 1.f / (1.f + expf(-(width - rel) * 5.f));
        sc[j] = sc[j] * scale - (1.f - m) * 10000.f;
        mx = fmaxf(mx, sc[j]);
    }
    float denom = 0.f;
    #pragma unroll
    for (int j = 0; j < KWIN; j++) {
        sc[j] = expf(sc[j] - mx);
        denom += sc[j];
    }
    const float inv = 1.f / denom;

    // acc = v_self, then += attn @ v_win
    float acc[16];
    {
        const uint4* vs = (const uint4*)(qkv + ((size_t)gwarp * 3 + 2) * CDIM);
        #pragma unroll
        for (int i = 0; i < 2; i++) unpack8(vs[lane + 32 * i], acc + 8 * i);
    }

    #pragma unroll
    for (int j = 0; j < KWIN; j++) {
        const int row = l + j - HALFK;
        if (row < 0 || row >= LSEQ) continue;
        const float a = sc[j] * inv;
        const uint4* v4 = (const uint4*)(qkv + ((size_t)(b * LSEQ + row) * 3 + 2) * CDIM);
        #pragma unroll
        for (int i = 0; i < 2; i++) {
            float vf[8];
            unpack8(v4[lane + 32 * i], vf);
            #pragma unroll
            for (int t = 0; t < 8; t++) acc[8 * i + t] += a * vf[t];
        }
    }

    // write hi/lo fp16 (uint4 = 8 halves per chunk)
    uint4* hrow = (uint4*)(att_hi + (size_t)gwarp * CDIM);
    uint4* lrow = (uint4*)(att_lo + (size_t)gwarp * CDIM);
    #pragma unroll
    for (int i = 0; i < 2; i++) {
        uint4 uh, ul;
        __half2* hh = (__half2*)&uh;
        __half2* ll = (__half2*)&ul;
        #pragma unroll
        for (int t = 0; t < 4; t++) {
            const float f0 = acc[8 * i + 2 * t];
            const float f1 = acc[8 * i + 2 * t + 1];
            const __half h0 = __float2half(f0);
            const __half h1 = __float2half(f1);
            hh[t] = __halves2half2(h0, h1);
            ll[t] = __halves2half2(__float2half(f0 - __half2float(h0)),
                                   __float2half(f1 - __half2float(h1)));
        }
        hrow[lane + 32 * i] = uh;
        lrow[lane + 32 * i] = ul;
    }
}

// ---------------------------------------------------------------------------
extern "C" void kernel_launch(void* const* d_in, const int* in_sizes, int n_in,
                              void* d_out, int out_size)
{
    const float* x       = (const float*)d_in[0];
    const float* w_qkv   = (const float*)d_in[1];
    const float* w_width = (const float*)d_in[2];
    const float* b_width = (const float*)d_in[3];
    const float* w_out   = (const float*)d_in[4];
    float* out = (float*)d_out;

    __half* qkvh; cudaGetSymbolAddress((void**)&qkvh, g_qkvh);
    __half* xhi;  cudaGetSymbolAddress((void**)&xhi,  g_xhi);
    __half* xlo;  cudaGetSymbolAddress((void**)&xlo,  g_xlo);
    __half* ahi;  cudaGetSymbolAddress((void**)&ahi,  g_ahi);
    __half* alo;  cudaGetSymbolAddress((void**)&alo,  g_alo);
    __half* wqhi; cudaGetSymbolAddress((void**)&wqhi, g_wqhi);
    __half* wohi; cudaGetSymbolAddress((void**)&wohi, g_wohi);

    cudaFuncSetAttribute(gemm_mma<__half>, cudaFuncAttributeMaxDynamicSharedMemorySize, GEMM_SMEM);
    cudaFuncSetAttribute(gemm_mma<float>,  cudaFuncAttributeMaxDynamicSharedMemorySize, GEMM_SMEM);

    // 0) input splits
    split_kernel<<<(NTOK * CDIM) / (256 * 4), 256>>>(x, xhi, xlo);
    {
        dim3 g(3 * CDIM / 32, CDIM / 32);
        wsplit_kernel<<<g, dim3(32, 8)>>>(w_qkv, wqhi, CDIM, 3 * CDIM);
    }
    {
        dim3 g(CDIM / 32, CDIM / 32);
        wsplit_kernel<<<g, dim3(32, 8)>>>(w_out, wohi, CDIM, CDIM);
    }

    // 1) qkv = x @ w_qkv   (2-term fp16 split, fp16 output)
    {
        dim3 grid(3 * CDIM / 128, NTOK / 128);
        gemm_mma<__half><<<grid, 256, GEMM_SMEM>>>(xhi, xlo, wqhi, qkvh, 3 * CDIM);
    }

    // 2) fused windowed attention (fp16 qkv) -> att hi/lo (fp16 split)
    attn_kernel<<<NTOK / 8, 256>>>(x, w_width, b_width, ahi, alo);

    // 3) out = att @ w_out  (2-term fp16 split, fp32 output)
    {
        dim3 grid(CDIM / 128, NTOK / 128);
        gemm_mma<float><<<grid, 256, GEMM_SMEM>>>(ahi, alo, wohi, out, CDIM);
    }
}